// round 6
// baseline (speedup 1.0000x reference)
#include <cuda_runtime.h>
#include <cuda_bf16.h>
#include <cstdint>

// Problem constants
#define D      64
#define K      1024
#define HW     4096        // 64*64
#define NROWS  131072      // 32*64*64
#define MT     128         // rows per block
#define NT     64          // codes per tile (16 tiles)
#define XPITCH 132         // padded pitch for xs (132*4=528B, 16B-multiple)
#define ES_T2  4096        // 64*64 float2 per e tile (32768 B)

// Output layout (concatenated, float32): quantized_out (b,c,h,w), loss (b,h,w,c), idx (b,h,w)
#define LOFF   8388608
#define IOFF   16777216

// Scratch (no cudaMalloc allowed)
__device__ float2 g_eT2[D * K]; // embedding transposed AND duplicated: [d][k] = {v,v}
__device__ float  g_e2[K];      // ||e_k||^2

__device__ __forceinline__ void cp_async16(uint32_t saddr, const void* gaddr) {
    asm volatile("cp.async.cg.shared.global [%0], [%1], 16;" :: "r"(saddr), "l"(gaddr) : "memory");
}
__device__ __forceinline__ void cp_commit() {
    asm volatile("cp.async.commit_group;" ::: "memory");
}

// ---------------------------------------------------------------------------
// Prep: transpose + duplicate embedding, row norms. Tiny, runs in a few us.
// ---------------------------------------------------------------------------
__global__ void vq_prep_kernel(const float* __restrict__ emb) {
    int k = blockIdx.x * blockDim.x + threadIdx.x;
    if (k < K) {
        float s = 0.0f;
#pragma unroll
        for (int d = 0; d < D; ++d) {
            float v = emb[k * D + d];
            g_eT2[d * K + k] = make_float2(v, v);
            s = fmaf(v, v, s);
        }
        g_e2[k] = s;
    }
}

// ---------------------------------------------------------------------------
// Main kernel. 128m x 64n per block, 256 threads, 8m x 4n per thread,
// f32x2 pairs packed along m (x pairs naturally adjacent). e operands arrive
// in smem PRE-DUPLICATED ({v,v} pairs) -> no mov.b64, no alu->fma cross-pipe
// dependency in the inner loop. Double-buffered e tiles via cp.async.
// ---------------------------------------------------------------------------
extern __shared__ float sm[];

__global__ __launch_bounds__(256, 2) void vq_main_kernel(
    const float* __restrict__ x,     // [b, c, h, w] fp32
    const float* __restrict__ emb,   // [K, D] fp32
    float* __restrict__ out)
{
    float*  xs  = sm;                      // [64][XPITCH]
    float2* es2 = (float2*)(sm + D * XPITCH); // [2][64][64] float2, duplicated e tiles
    __shared__ float rs[MT];               // row sums ||x||^2
    __shared__ float e2s[2][NT];           // code norms (double-buffered)
    __shared__ int   idxRow[MT];           // final argmin per row

    const int tid = threadIdx.x;
    const int p0  = blockIdx.x * MT;
    const int b   = p0 >> 12;
    const int s0  = p0 & 4095;
    const float* xbase = x + (size_t)b * 64 * HW + s0;

    const uint32_t es_u32  = (uint32_t)__cvta_generic_to_shared(es2);
    const uint32_t e2s_u32 = (uint32_t)__cvta_generic_to_shared(e2s);

    // ---- prefetch e tile 0: 64 d-rows x 32 chunks of 16B, 8 chunks/thread ----
    {
#pragma unroll
        for (int i = 0; i < 8; ++i) {
            int f = tid + i * 256;          // 2048 chunks
            int d = f >> 5, c = f & 31;
            cp_async16(es_u32 + (uint32_t)(d * 512 + c * 16),
                       g_eT2 + d * K + c * 2);
        }
        if (tid < 16)
            cp_async16(e2s_u32 + (uint32_t)(tid * 16), g_e2 + tid * 4);
        cp_commit();
    }

    // ---- load x tile with float4: per channel d, 128 contiguous floats ----
#pragma unroll
    for (int i = 0; i < 8; ++i) {
        int f = tid + i * 256;              // 2048 float4s
        int d = f >> 5, mf = f & 31;
        float4 v = *(const float4*)(xbase + d * HW + mf * 4);
        *(float4*)(xs + d * XPITCH + mf * 4) = v;
    }
    __syncthreads();

    // ---- per-row ||x||^2 (sequential d; uniform per-row shift, order benign) ----
    if (tid < MT) {
        float s = 0.0f;
#pragma unroll
        for (int d = 0; d < D; ++d) {
            float v = xs[d * XPITCH + tid];
            s = fmaf(v, v, s);
        }
        rs[tid] = s;
    }

    const int tx = tid & 15;   // n-group: codes tx*4 .. tx*4+3 within tile
    const int ty = tid >> 4;   // m-group: rows  ty*8 .. ty*8+7

    float bestv[8];
    int   besti[8];
#pragma unroll
    for (int i = 0; i < 8; ++i) { bestv[i] = 3.4e38f; besti[i] = 0; }

    for (int nt = 0; nt < K / NT; ++nt) {
        const int buf = nt & 1;
        __syncthreads();   // all warps done with tile nt-1 -> other buffer free (publishes rs/xs on nt=0)

        if (nt < K / NT - 1) {
            // prefetch tile nt+1 into the other buffer (pre-duplicated data)
            const float2* src = g_eT2 + (nt + 1) * NT;
            uint32_t dst = es_u32 + (uint32_t)(buf ^ 1) * (ES_T2 * 8);
#pragma unroll
            for (int i = 0; i < 8; ++i) {
                int f = tid + i * 256;
                int d = f >> 5, c = f & 31;
                cp_async16(dst + (uint32_t)(d * 512 + c * 16), src + d * K + c * 2);
            }
            if (tid < 16)
                cp_async16(e2s_u32 + (uint32_t)((buf ^ 1) * NT + tid * 4) * 4,
                           g_e2 + (nt + 1) * NT + tid * 4);
            cp_commit();
            asm volatile("cp.async.wait_group 1;" ::: "memory");   // tile nt complete
        } else {
            asm volatile("cp.async.wait_group 0;" ::: "memory");
        }
        __syncthreads();   // tile nt visible to all warps

        const float2* esb = es2 + buf * ES_T2;
        const float*  e2b = e2s[buf];

        // ---- 8m x 4n register tile, f32x2 packed along m; no movs ----
        unsigned long long acc[4][4];
#pragma unroll
        for (int mp = 0; mp < 4; ++mp)
#pragma unroll
            for (int j = 0; j < 4; ++j) acc[mp][j] = 0ULL;

#pragma unroll 8
        for (int d = 0; d < D; ++d) {
            const float* xrow = xs + d * XPITCH + ty * 8;
            ulonglong2 xA = *(const ulonglong2*)(xrow);       // rows (0,1),(2,3)
            ulonglong2 xB = *(const ulonglong2*)(xrow + 4);   // rows (4,5),(6,7)
            unsigned long long ax[4] = { xA.x, xA.y, xB.x, xB.y };

            // e: 4 codes, pre-duplicated {v,v} pairs -> direct 64-bit operands
            const ulonglong2* ep = (const ulonglong2*)(esb + d * NT + tx * 4);
            ulonglong2 eA = ep[0], eB = ep[1];
            unsigned long long en[4] = { eA.x, eA.y, eB.x, eB.y };

#pragma unroll
            for (int j = 0; j < 4; ++j)
#pragma unroll
                for (int mp = 0; mp < 4; ++mp)
                    asm("fma.rn.f32x2 %0, %1, %2, %0;"
                        : "+l"(acc[mp][j]) : "l"(ax[mp]), "l"(en[j]));
        }

        // ---- distances + running argmin (ascending n, strict < keeps first) ----
#pragma unroll
        for (int j = 0; j < 4; ++j) {
            int n = nt * NT + tx * 4 + j;
            float e2 = e2b[tx * 4 + j];
#pragma unroll
            for (int mp = 0; mp < 4; ++mp) {
                float2 dv = *(float2*)&acc[mp][j];
                // reference association: (||x||^2 + ||e||^2) - 2*dot, one rounding each
                float t0 = rs[ty * 8 + 2 * mp]     + e2;
                float t1 = rs[ty * 8 + 2 * mp + 1] + e2;
                float d0 = fmaf(dv.x, -2.0f, t0);
                float d1 = fmaf(dv.y, -2.0f, t1);
                if (d0 < bestv[2 * mp])     { bestv[2 * mp]     = d0; besti[2 * mp]     = n; }
                if (d1 < bestv[2 * mp + 1]) { bestv[2 * mp + 1] = d1; besti[2 * mp + 1] = n; }
            }
        }
    }

    // ---- cross-thread argmin reduce (reuse es2 region as scratch) ----
    __syncthreads();
    float* redv = (float*)es2;            // [128][16]
    int*   redi = (int*)((float*)es2 + 2048); // [128][16]
#pragma unroll
    for (int i = 0; i < 8; ++i) {
        int m = ty * 8 + i;
        redv[m * 16 + tx] = bestv[i];
        redi[m * 16 + tx] = besti[i];
    }
    __syncthreads();
    if (tid < MT) {
        float bv = redv[tid * 16];
        int   bi = redi[tid * 16];
#pragma unroll
        for (int t = 1; t < 16; ++t) {
            float v = redv[tid * 16 + t];
            int   ii = redi[tid * 16 + t];
            if (v < bv || (v == bv && ii < bi)) { bv = v; bi = ii; }
        }
        idxRow[tid] = bi;
        out[IOFF + p0 + tid] = (float)bi;   // idx as float (output dtype f32)
    }
    __syncthreads();

    // ---- loss (b,h,w,c): 64 contiguous floats per row ----
#pragma unroll
    for (int i = 0; i < 32; ++i) {
        int idx = tid + i * 256;
        int m = idx >> 6, c = idx & 63;
        float xv = xs[c * XPITCH + m];
        float ev = emb[idxRow[m] * D + c];
        float df = ev - xv;                 // (quantized - x), one rounding
        float t  = df * df;
        out[LOFF + (size_t)(p0 + m) * 64 + c] = t + 0.25f * t;  // == round(1.25*t)
    }

    // ---- quantized_out (b,c,h,w): per channel, 128 contiguous floats ----
#pragma unroll
    for (int i = 0; i < 32; ++i) {
        int idx = tid + i * 256;
        int c = idx >> 7, m = idx & 127;
        float xv = xs[c * XPITCH + m];
        float ev = emb[idxRow[m] * D + c];
        // straight-through: x + (q - x), NOT q (last-ulp fidelity to reference)
        out[(size_t)(b * 64 + c) * HW + s0 + m] = xv + (ev - xv);
    }
}

// ---------------------------------------------------------------------------
extern "C" void kernel_launch(void* const* d_in, const int* in_sizes, int n_in,
                              void* d_out, int out_size)
{
    const float* x_in = (const float*)d_in[0];   // inputs  [32,64,64,64]
    const float* emb  = (const float*)d_in[1];   // embedding [1024,64]
    float* out = (float*)d_out;

    static bool attr_set = false;
    // xs: 64*132*4 = 33792B, es2: 2*4096*8 = 65536B -> 99328B/CTA (2 CTAs)
    size_t smem_bytes = (size_t)(D * XPITCH * 4 + 2 * ES_T2 * 8);
    if (!attr_set) {
        cudaFuncSetAttribute(vq_main_kernel,
                             cudaFuncAttributeMaxDynamicSharedMemorySize,
                             (int)smem_bytes);
        attr_set = true;
    }

    vq_prep_kernel<<<4, 256>>>(emb);
    vq_main_kernel<<<NROWS / MT, 256, smem_bytes>>>(x_in, emb, out);
}

// round 8
// speedup vs baseline: 1.2126x; 1.2126x over previous
#include <cuda_runtime.h>
#include <cuda_bf16.h>
#include <cstdint>

// Problem constants
#define D      64
#define K      1024
#define HW     4096        // 64*64
#define NROWS  131072      // 32*64*64
#define MT     128         // rows per block
#define NT     64          // codes per tile (16 tiles)
#define XPITCH 132         // padded pitch for xs (epilogue bank-conflict kill)

// Output layout (concatenated, float32): quantized_out (b,c,h,w), loss (b,h,w,c), idx (b,h,w)
#define LOFF   8388608
#define IOFF   16777216

// Scratch (no cudaMalloc allowed)
__device__ float2 g_eT2[D * K]; // embedding transposed AND duplicated: [d][k] = {v,v}
__device__ float  g_e2[K];      // ||e_k||^2

__device__ __forceinline__ void cp_async16(uint32_t saddr, const void* gaddr) {
    asm volatile("cp.async.cg.shared.global [%0], [%1], 16;" :: "r"(saddr), "l"(gaddr) : "memory");
}
__device__ __forceinline__ void cp_commit() {
    asm volatile("cp.async.commit_group;" ::: "memory");
}

// ---------------------------------------------------------------------------
// Prep: transpose + duplicate embedding, row norms. Tiny, runs in a few us.
// ---------------------------------------------------------------------------
__global__ void vq_prep_kernel(const float* __restrict__ emb) {
    int k = blockIdx.x * blockDim.x + threadIdx.x;
    if (k < K) {
        float s = 0.0f;
#pragma unroll
        for (int d = 0; d < D; ++d) {
            float v = emb[k * D + d];
            g_eT2[d * K + k] = make_float2(v, v);
            s = fmaf(v, v, s);
        }
        g_e2[k] = s;
    }
}

// ---------------------------------------------------------------------------
// Main kernel. 128m x 64n per block, 256 threads, 8m x 4n per thread,
// f32x2 pairs packed along m (x pairs naturally adjacent). e operands arrive
// in smem PRE-DUPLICATED in a chunk-split layout:
//   chunk f = d*32 + j2*16 + tx  holds the 16B {e,e} pair-chunk for
//   codes tx*4 + j2*2 + {0,1}.
// -> each LDS.128 reads 16 lanes x 16B CONTIGUOUS (conflict-free), zero movs,
//    zero alu->fma cross-pipe chains in the inner loop.
// Single-buffered e tile (32KB) keeps smem at 66.5KB/CTA -> 3 CTAs/SM;
// tile-load exposure is hidden by the other two CTAs.
// ---------------------------------------------------------------------------
extern __shared__ float sm[];

__global__ __launch_bounds__(256, 3) void vq_main_kernel(
    const float* __restrict__ x,     // [b, c, h, w] fp32
    const float* __restrict__ emb,   // [K, D] fp32
    float* __restrict__ out)
{
    float* xs  = sm;                       // [64][XPITCH]
    char*  esb = (char*)(sm + D * XPITCH); // 32768B: 2048 chunks of 16B (dup e tile)
    __shared__ float rs[MT];               // row sums ||x||^2
    __shared__ float e2s[NT];              // code norms for current tile
    __shared__ int   idxRow[MT];           // final argmin per row

    const int tid = threadIdx.x;
    const int p0  = blockIdx.x * MT;
    const int b   = p0 >> 12;
    const int s0  = p0 & 4095;
    const float* xbase = x + (size_t)b * 64 * HW + s0;

    const uint32_t es_u32  = (uint32_t)__cvta_generic_to_shared(esb);
    const uint32_t e2s_u32 = (uint32_t)__cvta_generic_to_shared(e2s);

    // ---- load x tile with float4: per channel d, 128 contiguous floats ----
#pragma unroll
    for (int i = 0; i < 8; ++i) {
        int f = tid + i * 256;              // 2048 float4s
        int d = f >> 5, mf = f & 31;
        float4 v = *(const float4*)(xbase + d * HW + mf * 4);
        *(float4*)(xs + d * XPITCH + mf * 4) = v;
    }
    __syncthreads();

    // ---- per-row ||x||^2 (sequential d; uniform per-row shift, order benign) ----
    if (tid < MT) {
        float s = 0.0f;
#pragma unroll
        for (int d = 0; d < D; ++d) {
            float v = xs[d * XPITCH + tid];
            s = fmaf(v, v, s);
        }
        rs[tid] = s;
    }

    const int tx = tid & 15;   // n-group: codes tx*4 .. tx*4+3 within tile
    const int ty = tid >> 4;   // m-group: rows  ty*8 .. ty*8+7

    float bestv[8];
    int   besti[8];
#pragma unroll
    for (int i = 0; i < 8; ++i) { bestv[i] = 3.4e38f; besti[i] = 0; }

    for (int nt = 0; nt < K / NT; ++nt) {
        __syncthreads();   // previous tile's compute done -> es/e2s reusable
                           // (on nt=0 this also publishes xs and rs)

        // ---- fill dup e tile, chunk-linear: dst chunk f <- codes per (d,j2,tx) ----
        {
            const float2* src = g_eT2 + nt * NT;   // duplicated, transposed
#pragma unroll
            for (int i = 0; i < 8; ++i) {
                int f = tid + i * 256;             // 2048 chunks
                int d = f >> 5, rem = f & 31;
                int j2 = rem >> 4, tc = rem & 15;
                cp_async16(es_u32 + (uint32_t)f * 16,
                           src + d * K + tc * 4 + j2 * 2);
            }
            if (tid < 16)
                cp_async16(e2s_u32 + (uint32_t)tid * 16, g_e2 + nt * NT + tid * 4);
            cp_commit();
            asm volatile("cp.async.wait_group 0;" ::: "memory");
        }
        __syncthreads();   // tile visible to all warps

        // ---- 8m x 4n register tile, f32x2 packed along m; no movs ----
        unsigned long long acc[4][4];
#pragma unroll
        for (int mp = 0; mp < 4; ++mp)
#pragma unroll
            for (int j = 0; j < 4; ++j) acc[mp][j] = 0ULL;

#pragma unroll 4
        for (int d = 0; d < D; ++d) {
            const float* xrow = xs + d * XPITCH + ty * 8;
            ulonglong2 xA = *(const ulonglong2*)(xrow);       // rows (0,1),(2,3)
            ulonglong2 xB = *(const ulonglong2*)(xrow + 4);   // rows (4,5),(6,7)
            unsigned long long ax[4] = { xA.x, xA.y, xB.x, xB.y };

            // e: 4 codes = 2 chunk-split 16B loads, contiguous across lanes
            ulonglong2 eA = *(const ulonglong2*)(esb + (d * 32 + tx) * 16);
            ulonglong2 eB = *(const ulonglong2*)(esb + (d * 32 + 16 + tx) * 16);
            unsigned long long en[4] = { eA.x, eA.y, eB.x, eB.y };

#pragma unroll
            for (int j = 0; j < 4; ++j)
#pragma unroll
                for (int mp = 0; mp < 4; ++mp)
                    asm("fma.rn.f32x2 %0, %1, %2, %0;"
                        : "+l"(acc[mp][j]) : "l"(ax[mp]), "l"(en[j]));
        }

        // ---- distances + running argmin (ascending n, strict < keeps first) ----
#pragma unroll
        for (int j = 0; j < 4; ++j) {
            int n = nt * NT + tx * 4 + j;
            float e2 = e2s[tx * 4 + j];
#pragma unroll
            for (int mp = 0; mp < 4; ++mp) {
                float2 dv = *(float2*)&acc[mp][j];
                // reference association: (||x||^2 + ||e||^2) - 2*dot, one rounding each
                float t0 = rs[ty * 8 + 2 * mp]     + e2;
                float t1 = rs[ty * 8 + 2 * mp + 1] + e2;
                float d0 = fmaf(dv.x, -2.0f, t0);
                float d1 = fmaf(dv.y, -2.0f, t1);
                if (d0 < bestv[2 * mp])     { bestv[2 * mp]     = d0; besti[2 * mp]     = n; }
                if (d1 < bestv[2 * mp + 1]) { bestv[2 * mp + 1] = d1; besti[2 * mp + 1] = n; }
            }
        }
    }

    // ---- cross-thread argmin reduce (reuse e-tile region as scratch: 16KB <= 32KB) ----
    __syncthreads();
    float* redv = (float*)esb;            // [128][16]
    int*   redi = (int*)(esb + 8192);     // [128][16]
#pragma unroll
    for (int i = 0; i < 8; ++i) {
        int m = ty * 8 + i;
        redv[m * 16 + tx] = bestv[i];
        redi[m * 16 + tx] = besti[i];
    }
    __syncthreads();
    if (tid < MT) {
        float bv = redv[tid * 16];
        int   bi = redi[tid * 16];
#pragma unroll
        for (int t = 1; t < 16; ++t) {
            float v = redv[tid * 16 + t];
            int   ii = redi[tid * 16 + t];
            if (v < bv || (v == bv && ii < bi)) { bv = v; bi = ii; }
        }
        idxRow[tid] = bi;
        out[IOFF + p0 + tid] = (float)bi;   // idx as float (output dtype f32)
    }
    __syncthreads();

    // ---- loss (b,h,w,c): 64 contiguous floats per row ----
#pragma unroll
    for (int i = 0; i < 32; ++i) {
        int idx = tid + i * 256;
        int m = idx >> 6, c = idx & 63;
        float xv = xs[c * XPITCH + m];
        float ev = emb[idxRow[m] * D + c];
        float df = ev - xv;                 // (quantized - x), one rounding
        float t  = df * df;
        out[LOFF + (size_t)(p0 + m) * 64 + c] = t + 0.25f * t;  // == round(1.25*t)
    }

    // ---- quantized_out (b,c,h,w): per channel, 128 contiguous floats ----
#pragma unroll
    for (int i = 0; i < 32; ++i) {
        int idx = tid + i * 256;
        int c = idx >> 7, m = idx & 127;
        float xv = xs[c * XPITCH + m];
        float ev = emb[idxRow[m] * D + c];
        // straight-through: x + (q - x), NOT q (last-ulp fidelity to reference)
        out[(size_t)(b * 64 + c) * HW + s0 + m] = xv + (ev - xv);
    }
}

// ---------------------------------------------------------------------------
extern "C" void kernel_launch(void* const* d_in, const int* in_sizes, int n_in,
                              void* d_out, int out_size)
{
    const float* x_in = (const float*)d_in[0];   // inputs  [32,64,64,64]
    const float* emb  = (const float*)d_in[1];   // embedding [1024,64]
    float* out = (float*)d_out;

    static bool attr_set = false;
    // xs: 64*132*4 = 33792B, dup e tile: 32768B -> 66560B/CTA (3 CTAs ~= 200KB)
    size_t smem_bytes = (size_t)(D * XPITCH * 4 + 32768);
    if (!attr_set) {
        cudaFuncSetAttribute(vq_main_kernel,
                             cudaFuncAttributeMaxDynamicSharedMemorySize,
                             (int)smem_bytes);
        attr_set = true;
    }

    vq_prep_kernel<<<4, 256>>>(emb);
    vq_main_kernel<<<NROWS / MT, 256, smem_bytes>>>(x_in, emb, out);
}

// round 9
// speedup vs baseline: 1.2376x; 1.0206x over previous
#include <cuda_runtime.h>
#include <cuda_bf16.h>
#include <cstdint>

// Problem constants
#define D      64
#define K      1024
#define HW     4096        // 64*64
#define NROWS  131072      // 32*64*64
#define MT     128         // rows per block
#define NT     64          // codes per tile (16 tiles)
#define XPITCH 132         // padded pitch for xs (epilogue bank-conflict kill)
#define ES_BYTES 32768     // one dup e tile: 64 d x 32 chunks x 16B

// Output layout (concatenated, float32): quantized_out (b,c,h,w), loss (b,h,w,c), idx (b,h,w)
#define LOFF   8388608
#define IOFF   16777216

// Scratch (no cudaMalloc allowed)
__device__ float2 g_eT2[D * K]; // embedding transposed AND duplicated: [d][k] = {v,v}
__device__ float  g_e2[K];      // ||e_k||^2

__device__ __forceinline__ void cp_async16(uint32_t saddr, const void* gaddr) {
    asm volatile("cp.async.cg.shared.global [%0], [%1], 16;" :: "r"(saddr), "l"(gaddr) : "memory");
}
__device__ __forceinline__ void cp_commit() {
    asm volatile("cp.async.commit_group;" ::: "memory");
}

// ---------------------------------------------------------------------------
// Prep: transpose + duplicate embedding, row norms. Tiny, runs in a few us.
// ---------------------------------------------------------------------------
__global__ void vq_prep_kernel(const float* __restrict__ emb) {
    int k = blockIdx.x * blockDim.x + threadIdx.x;
    if (k < K) {
        float s = 0.0f;
#pragma unroll
        for (int d = 0; d < D; ++d) {
            float v = emb[k * D + d];
            g_eT2[d * K + k] = make_float2(v, v);
            s = fmaf(v, v, s);
        }
        g_e2[k] = s;
    }
}

// ---------------------------------------------------------------------------
// Main kernel. 128m x 64n per block, 256 threads, 8m x 4n per thread,
// f32x2 pairs packed along m (x pairs naturally adjacent).
// e operands PRE-DUPLICATED in smem, chunk-split layout:
//   chunk f = d*32 + j2*16 + tx  holds the 16B {e,e}x2 pair-chunk for
//   codes tx*4 + j2*2 + {0,1} at depth d
// -> each LDS.128 reads 16 lanes x 16B CONTIGUOUS (conflict-free), zero movs,
//    zero alu->fma cross-pipe chains in the inner loop.
// DOUBLE-BUFFERED via cp.async (wait_group 1) so tile reloads overlap compute.
// ---------------------------------------------------------------------------
extern __shared__ float sm[];

__global__ __launch_bounds__(256, 2) void vq_main_kernel(
    const float* __restrict__ x,     // [b, c, h, w] fp32
    const float* __restrict__ emb,   // [K, D] fp32
    float* __restrict__ out)
{
    float* xs  = sm;                       // [64][XPITCH]
    char*  es  = (char*)(sm + D * XPITCH); // [2][32768] double-buffered dup e tiles
    __shared__ float rs[MT];               // row sums ||x||^2
    __shared__ float e2s[2][NT];           // code norms (double-buffered)
    __shared__ int   idxRow[MT];           // final argmin per row

    const int tid = threadIdx.x;
    const int p0  = blockIdx.x * MT;
    const int b   = p0 >> 12;
    const int s0  = p0 & 4095;
    const float* xbase = x + (size_t)b * 64 * HW + s0;

    const uint32_t es_u32  = (uint32_t)__cvta_generic_to_shared(es);
    const uint32_t e2s_u32 = (uint32_t)__cvta_generic_to_shared(e2s);

    // ---- prefetch e tile 0 into buffer 0 (chunk-split layout) ----
    {
        const float2* src = g_eT2;          // tile 0
#pragma unroll
        for (int i = 0; i < 8; ++i) {
            int f = tid + i * 256;          // 2048 chunks
            int d = f >> 5, rem = f & 31;
            int j2 = rem >> 4, tc = rem & 15;
            cp_async16(es_u32 + (uint32_t)f * 16, src + d * K + tc * 4 + j2 * 2);
        }
        if (tid < 16)
            cp_async16(e2s_u32 + (uint32_t)tid * 16, g_e2 + tid * 4);
        cp_commit();
    }

    // ---- load x tile with float4: per channel d, 128 contiguous floats ----
#pragma unroll
    for (int i = 0; i < 8; ++i) {
        int f = tid + i * 256;              // 2048 float4s
        int d = f >> 5, mf = f & 31;
        float4 v = *(const float4*)(xbase + d * HW + mf * 4);
        *(float4*)(xs + d * XPITCH + mf * 4) = v;
    }
    __syncthreads();

    // ---- per-row ||x||^2 (sequential d; uniform per-row shift, order benign) ----
    if (tid < MT) {
        float s = 0.0f;
#pragma unroll
        for (int d = 0; d < D; ++d) {
            float v = xs[d * XPITCH + tid];
            s = fmaf(v, v, s);
        }
        rs[tid] = s;
    }

    const int tx = tid & 15;   // n-group: codes tx*4 .. tx*4+3 within tile
    const int ty = tid >> 4;   // m-group: rows  ty*8 .. ty*8+7

    float bestv[8];
    int   besti[8];
#pragma unroll
    for (int i = 0; i < 8; ++i) { bestv[i] = 3.4e38f; besti[i] = 0; }

    for (int nt = 0; nt < K / NT; ++nt) {
        const int buf = nt & 1;
        __syncthreads();   // all warps done with tile nt-1 -> other buffer free
                           // (on nt=0 this also publishes xs and rs)

        if (nt < K / NT - 1) {
            // prefetch tile nt+1 into the other buffer (chunk-split, pre-dup)
            const float2* src = g_eT2 + (nt + 1) * NT;
            uint32_t dst = es_u32 + (uint32_t)(buf ^ 1) * ES_BYTES;
#pragma unroll
            for (int i = 0; i < 8; ++i) {
                int f = tid + i * 256;
                int d = f >> 5, rem = f & 31;
                int j2 = rem >> 4, tc = rem & 15;
                cp_async16(dst + (uint32_t)f * 16, src + d * K + tc * 4 + j2 * 2);
            }
            if (tid < 16)
                cp_async16(e2s_u32 + (uint32_t)((buf ^ 1) * NT + tid * 4) * 4,
                           g_e2 + (nt + 1) * NT + tid * 4);
            cp_commit();
            asm volatile("cp.async.wait_group 1;" ::: "memory");   // tile nt complete
        } else {
            asm volatile("cp.async.wait_group 0;" ::: "memory");
        }
        __syncthreads();   // tile nt visible to all warps

        const char*  esb = es + buf * ES_BYTES;
        const float* e2b = e2s[buf];

        // ---- 8m x 4n register tile, f32x2 packed along m; no movs ----
        unsigned long long acc[4][4];
#pragma unroll
        for (int mp = 0; mp < 4; ++mp)
#pragma unroll
            for (int j = 0; j < 4; ++j) acc[mp][j] = 0ULL;

#pragma unroll 4
        for (int d = 0; d < D; ++d) {
            const float* xrow = xs + d * XPITCH + ty * 8;
            ulonglong2 xA = *(const ulonglong2*)(xrow);       // rows (0,1),(2,3)
            ulonglong2 xB = *(const ulonglong2*)(xrow + 4);   // rows (4,5),(6,7)
            unsigned long long ax[4] = { xA.x, xA.y, xB.x, xB.y };

            // e: 4 codes = 2 chunk-split LDS.128, contiguous across 16 lanes
            ulonglong2 eA = *(const ulonglong2*)(esb + (d * 32 + tx) * 16);
            ulonglong2 eB = *(const ulonglong2*)(esb + (d * 32 + 16 + tx) * 16);
            unsigned long long en[4] = { eA.x, eA.y, eB.x, eB.y };

#pragma unroll
            for (int j = 0; j < 4; ++j)
#pragma unroll
                for (int mp = 0; mp < 4; ++mp)
                    asm("fma.rn.f32x2 %0, %1, %2, %0;"
                        : "+l"(acc[mp][j]) : "l"(ax[mp]), "l"(en[j]));
        }

        // ---- distances + running argmin (ascending n, strict < keeps first) ----
#pragma unroll
        for (int j = 0; j < 4; ++j) {
            int n = nt * NT + tx * 4 + j;
            float e2 = e2b[tx * 4 + j];
#pragma unroll
            for (int mp = 0; mp < 4; ++mp) {
                float2 dv = *(float2*)&acc[mp][j];
                // reference association: (||x||^2 + ||e||^2) - 2*dot, one rounding each
                float t0 = rs[ty * 8 + 2 * mp]     + e2;
                float t1 = rs[ty * 8 + 2 * mp + 1] + e2;
                float d0 = fmaf(dv.x, -2.0f, t0);
                float d1 = fmaf(dv.y, -2.0f, t1);
                if (d0 < bestv[2 * mp])     { bestv[2 * mp]     = d0; besti[2 * mp]     = n; }
                if (d1 < bestv[2 * mp + 1]) { bestv[2 * mp + 1] = d1; besti[2 * mp + 1] = n; }
            }
        }
    }

    // ---- cross-thread argmin reduce (reuse e-tile region as scratch) ----
    __syncthreads();
    float* redv = (float*)es;             // [128][16]
    int*   redi = (int*)(es + 8192);      // [128][16]
#pragma unroll
    for (int i = 0; i < 8; ++i) {
        int m = ty * 8 + i;
        redv[m * 16 + tx] = bestv[i];
        redi[m * 16 + tx] = besti[i];
    }
    __syncthreads();
    if (tid < MT) {
        float bv = redv[tid * 16];
        int   bi = redi[tid * 16];
#pragma unroll
        for (int t = 1; t < 16; ++t) {
            float v = redv[tid * 16 + t];
            int   ii = redi[tid * 16 + t];
            if (v < bv || (v == bv && ii < bi)) { bv = v; bi = ii; }
        }
        idxRow[tid] = bi;
        out[IOFF + p0 + tid] = (float)bi;   // idx as float (output dtype f32)
    }
    __syncthreads();

    // ---- loss (b,h,w,c): 64 contiguous floats per row ----
#pragma unroll
    for (int i = 0; i < 32; ++i) {
        int idx = tid + i * 256;
        int m = idx >> 6, c = idx & 63;
        float xv = xs[c * XPITCH + m];
        float ev = emb[idxRow[m] * D + c];
        float df = ev - xv;                 // (quantized - x), one rounding
        float t  = df * df;
        out[LOFF + (size_t)(p0 + m) * 64 + c] = t + 0.25f * t;  // == round(1.25*t)
    }

    // ---- quantized_out (b,c,h,w): per channel, 128 contiguous floats ----
#pragma unroll
    for (int i = 0; i < 32; ++i) {
        int idx = tid + i * 256;
        int c = idx >> 7, m = idx & 127;
        float xv = xs[c * XPITCH + m];
        float ev = emb[idxRow[m] * D + c];
        // straight-through: x + (q - x), NOT q (last-ulp fidelity to reference)
        out[(size_t)(b * 64 + c) * HW + s0 + m] = xv + (ev - xv);
    }
}

// ---------------------------------------------------------------------------
extern "C" void kernel_launch(void* const* d_in, const int* in_sizes, int n_in,
                              void* d_out, int out_size)
{
    const float* x_in = (const float*)d_in[0];   // inputs  [32,64,64,64]
    const float* emb  = (const float*)d_in[1];   // embedding [1024,64]
    float* out = (float*)d_out;

    static bool attr_set = false;
    // xs: 64*132*4 = 33792B, dup e tiles: 2*32768B -> 99328B/CTA (2 CTAs)
    size_t smem_bytes = (size_t)(D * XPITCH * 4 + 2 * ES_BYTES);
    if (!attr_set) {
        cudaFuncSetAttribute(vq_main_kernel,
                             cudaFuncAttributeMaxDynamicSharedMemorySize,
                             (int)smem_bytes);
        attr_set = true;
    }

    vq_prep_kernel<<<4, 256>>>(emb);
    vq_main_kernel<<<NROWS / MT, 256, smem_bytes>>>(x_in, emb, out);
}

// round 10
// speedup vs baseline: 1.2419x; 1.0035x over previous
#include <cuda_runtime.h>
#include <cuda_bf16.h>
#include <cstdint>

// Problem constants
#define D      64
#define K      1024
#define HW     4096        // 64*64
#define NROWS  131072      // 32*64*64
#define MT     128         // rows per block
#define NT     64          // codes per tile (16 tiles)
#define XPITCH 132         // padded pitch for xs (epilogue bank-conflict kill)
#define ES_BYTES 32768     // one dup e tile: 64 d x 32 chunks x 16B

// Output layout (concatenated, float32): quantized_out (b,c,h,w), loss (b,h,w,c), idx (b,h,w)
#define LOFF   8388608
#define IOFF   16777216

// Scratch (no cudaMalloc allowed)
__device__ float2 g_eT2[D * K]; // embedding transposed AND duplicated: [d][k] = {v,v}
__device__ float  g_e2[K];      // ||e_k||^2

__device__ __forceinline__ void cp_async16(uint32_t saddr, const void* gaddr) {
    asm volatile("cp.async.cg.shared.global [%0], [%1], 16;" :: "r"(saddr), "l"(gaddr) : "memory");
}
__device__ __forceinline__ void cp_commit() {
    asm volatile("cp.async.commit_group;" ::: "memory");
}

// ---------------------------------------------------------------------------
// Prep: transpose + duplicate embedding, row norms. Tiny, runs in a few us.
// ---------------------------------------------------------------------------
__global__ void vq_prep_kernel(const float* __restrict__ emb) {
    int k = blockIdx.x * blockDim.x + threadIdx.x;
    if (k < K) {
        float s = 0.0f;
#pragma unroll
        for (int d = 0; d < D; ++d) {
            float v = emb[k * D + d];
            g_eT2[d * K + k] = make_float2(v, v);
            s = fmaf(v, v, s);
        }
        g_e2[k] = s;
    }
}

// ---------------------------------------------------------------------------
// Main kernel. 128m x 64n per block, 256 threads, 8m x 4n per thread,
// f32x2 pairs packed along m (x pairs naturally adjacent).
// e operands PRE-DUPLICATED in smem, chunk-split layout:
//   chunk f = d*32 + j2*16 + tx  holds the 16B {e,e}x2 pair-chunk for
//   codes tx*4 + j2*2 + {0,1} at depth d
// -> each LDS.128 reads 16 lanes x 16B CONTIGUOUS (conflict-free), zero movs,
//    zero alu->fma cross-pipe chains in the inner loop.
// DOUBLE-BUFFERED via cp.async (wait_group 1) so tile reloads overlap compute.
// ---------------------------------------------------------------------------
extern __shared__ float sm[];

__global__ __launch_bounds__(256, 2) void vq_main_kernel(
    const float* __restrict__ x,     // [b, c, h, w] fp32
    const float* __restrict__ emb,   // [K, D] fp32
    float* __restrict__ out)
{
    float* xs  = sm;                       // [64][XPITCH]
    char*  es  = (char*)(sm + D * XPITCH); // [2][32768] double-buffered dup e tiles
    __shared__ float rs[MT];               // row sums ||x||^2
    __shared__ float e2s[2][NT];           // code norms (double-buffered)
    __shared__ int   idxRow[MT];           // final argmin per row

    const int tid = threadIdx.x;
    const int p0  = blockIdx.x * MT;
    const int b   = p0 >> 12;
    const int s0  = p0 & 4095;
    const float* xbase = x + (size_t)b * 64 * HW + s0;

    const uint32_t es_u32  = (uint32_t)__cvta_generic_to_shared(es);
    const uint32_t e2s_u32 = (uint32_t)__cvta_generic_to_shared(e2s);

    // ---- prefetch e tile 0 into buffer 0 (chunk-split layout) ----
    {
        const float2* src = g_eT2;          // tile 0
#pragma unroll
        for (int i = 0; i < 8; ++i) {
            int f = tid + i * 256;          // 2048 chunks
            int d = f >> 5, rem = f & 31;
            int j2 = rem >> 4, tc = rem & 15;
            cp_async16(es_u32 + (uint32_t)f * 16, src + d * K + tc * 4 + j2 * 2);
        }
        if (tid < 16)
            cp_async16(e2s_u32 + (uint32_t)tid * 16, g_e2 + tid * 4);
        cp_commit();
    }

    // ---- load x tile with float4: per channel d, 128 contiguous floats ----
#pragma unroll
    for (int i = 0; i < 8; ++i) {
        int f = tid + i * 256;              // 2048 float4s
        int d = f >> 5, mf = f & 31;
        float4 v = *(const float4*)(xbase + d * HW + mf * 4);
        *(float4*)(xs + d * XPITCH + mf * 4) = v;
    }
    __syncthreads();

    // ---- per-row ||x||^2 (sequential d; uniform per-row shift, order benign) ----
    if (tid < MT) {
        float s = 0.0f;
#pragma unroll
        for (int d = 0; d < D; ++d) {
            float v = xs[d * XPITCH + tid];
            s = fmaf(v, v, s);
        }
        rs[tid] = s;
    }

    const int tx = tid & 15;   // n-group: codes tx*4 .. tx*4+3 within tile
    const int ty = tid >> 4;   // m-group: rows  ty*8 .. ty*8+7

    float bestv[8];
    int   besti[8];
#pragma unroll
    for (int i = 0; i < 8; ++i) { bestv[i] = 3.4e38f; besti[i] = 0; }

    for (int nt = 0; nt < K / NT; ++nt) {
        const int buf = nt & 1;
        __syncthreads();   // all warps done with tile nt-1 -> other buffer free
                           // (on nt=0 this also publishes xs and rs)

        if (nt < K / NT - 1) {
            // prefetch tile nt+1 into the other buffer (chunk-split, pre-dup)
            const float2* src = g_eT2 + (nt + 1) * NT;
            uint32_t dst = es_u32 + (uint32_t)(buf ^ 1) * ES_BYTES;
#pragma unroll
            for (int i = 0; i < 8; ++i) {
                int f = tid + i * 256;
                int d = f >> 5, rem = f & 31;
                int j2 = rem >> 4, tc = rem & 15;
                cp_async16(dst + (uint32_t)f * 16, src + d * K + tc * 4 + j2 * 2);
            }
            if (tid < 16)
                cp_async16(e2s_u32 + (uint32_t)((buf ^ 1) * NT + tid * 4) * 4,
                           g_e2 + (nt + 1) * NT + tid * 4);
            cp_commit();
            asm volatile("cp.async.wait_group 1;" ::: "memory");   // tile nt complete
        } else {
            asm volatile("cp.async.wait_group 0;" ::: "memory");
        }
        __syncthreads();   // tile nt visible to all warps

        const char*  esb = es + buf * ES_BYTES;
        const float* e2b = e2s[buf];

        // ---- 8m x 4n register tile, f32x2 packed along m; no movs ----
        unsigned long long acc[4][4];
#pragma unroll
        for (int mp = 0; mp < 4; ++mp)
#pragma unroll
            for (int j = 0; j < 4; ++j) acc[mp][j] = 0ULL;

#pragma unroll 4
        for (int d = 0; d < D; ++d) {
            const float* xrow = xs + d * XPITCH + ty * 8;
            ulonglong2 xA = *(const ulonglong2*)(xrow);       // rows (0,1),(2,3)
            ulonglong2 xB = *(const ulonglong2*)(xrow + 4);   // rows (4,5),(6,7)
            unsigned long long ax[4] = { xA.x, xA.y, xB.x, xB.y };

            // e: 4 codes = 2 chunk-split LDS.128, contiguous across 16 lanes
            ulonglong2 eA = *(const ulonglong2*)(esb + (d * 32 + tx) * 16);
            ulonglong2 eB = *(const ulonglong2*)(esb + (d * 32 + 16 + tx) * 16);
            unsigned long long en[4] = { eA.x, eA.y, eB.x, eB.y };

#pragma unroll
            for (int j = 0; j < 4; ++j)
#pragma unroll
                for (int mp = 0; mp < 4; ++mp)
                    asm("fma.rn.f32x2 %0, %1, %2, %0;"
                        : "+l"(acc[mp][j]) : "l"(ax[mp]), "l"(en[j]));
        }

        // ---- distances + running argmin (ascending n, strict < keeps first) ----
#pragma unroll
        for (int j = 0; j < 4; ++j) {
            int n = nt * NT + tx * 4 + j;
            float e2 = e2b[tx * 4 + j];
#pragma unroll
            for (int mp = 0; mp < 4; ++mp) {
                float2 dv = *(float2*)&acc[mp][j];
                // reference association: (||x||^2 + ||e||^2) - 2*dot, one rounding each
                float t0 = rs[ty * 8 + 2 * mp]     + e2;
                float t1 = rs[ty * 8 + 2 * mp + 1] + e2;
                float d0 = fmaf(dv.x, -2.0f, t0);
                float d1 = fmaf(dv.y, -2.0f, t1);
                if (d0 < bestv[2 * mp])     { bestv[2 * mp]     = d0; besti[2 * mp]     = n; }
                if (d1 < bestv[2 * mp + 1]) { bestv[2 * mp + 1] = d1; besti[2 * mp + 1] = n; }
            }
        }
    }

    // ---- cross-thread argmin reduce (reuse e-tile region as scratch) ----
    __syncthreads();
    float* redv = (float*)es;             // [128][16]
    int*   redi = (int*)(es + 8192);      // [128][16]
#pragma unroll
    for (int i = 0; i < 8; ++i) {
        int m = ty * 8 + i;
        redv[m * 16 + tx] = bestv[i];
        redi[m * 16 + tx] = besti[i];
    }
    __syncthreads();
    if (tid < MT) {
        float bv = redv[tid * 16];
        int   bi = redi[tid * 16];
#pragma unroll
        for (int t = 1; t < 16; ++t) {
            float v = redv[tid * 16 + t];
            int   ii = redi[tid * 16 + t];
            if (v < bv || (v == bv && ii < bi)) { bv = v; bi = ii; }
        }
        idxRow[tid] = bi;
        out[IOFF + p0 + tid] = (float)bi;   // idx as float (output dtype f32)
    }
    __syncthreads();

    // ---- loss (b,h,w,c): 64 contiguous floats per row ----
#pragma unroll
    for (int i = 0; i < 32; ++i) {
        int idx = tid + i * 256;
        int m = idx >> 6, c = idx & 63;
        float xv = xs[c * XPITCH + m];
        float ev = emb[idxRow[m] * D + c];
        float df = ev - xv;                 // (quantized - x), one rounding
        float t  = df * df;
        out[LOFF + (size_t)(p0 + m) * 64 + c] = t + 0.25f * t;  // == round(1.25*t)
    }

    // ---- quantized_out (b,c,h,w): per channel, 128 contiguous floats ----
#pragma unroll
    for (int i = 0; i < 32; ++i) {
        int idx = tid + i * 256;
        int c = idx >> 7, m = idx & 127;
        float xv = xs[c * XPITCH + m];
        float ev = emb[idxRow[m] * D + c];
        // straight-through: x + (q - x), NOT q (last-ulp fidelity to reference)
        out[(size_t)(b * 64 + c) * HW + s0 + m] = xv + (ev - xv);
    }
}

// ---------------------------------------------------------------------------
extern "C" void kernel_launch(void* const* d_in, const int* in_sizes, int n_in,
                              void* d_out, int out_size)
{
    const float* x_in = (const float*)d_in[0];   // inputs  [32,64,64,64]
    const float* emb  = (const float*)d_in[1];   // embedding [1024,64]
    float* out = (float*)d_out;

    static bool attr_set = false;
    // xs: 64*132*4 = 33792B, dup e tiles: 2*32768B -> 99328B/CTA (2 CTAs)
    size_t smem_bytes = (size_t)(D * XPITCH * 4 + 2 * ES_BYTES);
    if (!attr_set) {
        cudaFuncSetAttribute(vq_main_kernel,
                             cudaFuncAttributeMaxDynamicSharedMemorySize,
                             (int)smem_bytes);
        attr_set = true;
    }

    vq_prep_kernel<<<4, 256>>>(emb);
    vq_main_kernel<<<NROWS / MT, 256, smem_bytes>>>(x_in, emb, out);
}

// round 11
// speedup vs baseline: 1.7944x; 1.4449x over previous
#include <cuda_runtime.h>
#include <cuda_bf16.h>
#include <cstdint>

// Problem constants
#define D      64
#define K      1024
#define HW     4096        // 64*64
#define NROWS  131072      // 32*64*64
#define MT     128         // rows per block
#define NT     64          // codes per tile (16 tiles)
#define XPITCH 132         // padded pitch for xs (132*4=528B, 16B-multiple)
#define ES_TILE 4096       // 64*64 floats per e tile

// Output layout (concatenated, float32): quantized_out (b,c,h,w), loss (b,h,w,c), idx (b,h,w)
#define LOFF   8388608
#define IOFF   16777216

// Scratch (no cudaMalloc allowed)
__device__ float g_eT[D * K];   // embedding transposed [d][k]
__device__ float g_e2[K];       // ||e_k||^2

__device__ __forceinline__ void cp_async16(uint32_t saddr, const void* gaddr) {
    asm volatile("cp.async.cg.shared.global [%0], [%1], 16;" :: "r"(saddr), "l"(gaddr) : "memory");
}
__device__ __forceinline__ void cp_commit() {
    asm volatile("cp.async.commit_group;" ::: "memory");
}

// ---------------------------------------------------------------------------
// Prep, parallelized (~1-2us instead of latency-bound ~8us):
//  blocks 0..255:  element-parallel transpose, one (d,k) per thread,
//                  output-linear mapping -> coalesced STG.
//  blocks 256..259: e2 per code k: 16 parallel float4 LDGs, then the
//                  sequential d=0..63 fmaf chain (EXACT same order as before
//                  -> bit-identical g_e2, argmin unaffected).
// ---------------------------------------------------------------------------
__global__ void vq_prep_kernel(const float* __restrict__ emb) {
    int gid = blockIdx.x * 256 + threadIdx.x;
    if (blockIdx.x < 256) {
        // gid = d*K + k  (k fastest across lanes -> coalesced write)
        int d = gid >> 10, k = gid & 1023;
        g_eT[gid] = emb[k * D + d];
    } else {
        int k = gid - 65536;               // 0..1023
        float4 v[16];
        const float4* row = (const float4*)(emb + k * D);
#pragma unroll
        for (int i = 0; i < 16; ++i) v[i] = row[i];   // 16 independent LDG.128
        float s = 0.0f;
#pragma unroll
        for (int i = 0; i < 16; ++i) {     // sequential order d=0..63, as before
            s = fmaf(v[i].x, v[i].x, s);
            s = fmaf(v[i].y, v[i].y, s);
            s = fmaf(v[i].z, v[i].z, s);
            s = fmaf(v[i].w, v[i].w, s);
        }
        g_e2[k] = s;
    }
}

// ---------------------------------------------------------------------------
// Main kernel: R5 VERBATIM (proven 352us main, ~99% of the rt=3 f32x2
// RF-bank roofline). 128m x 64n per block, 256 threads, 8m x 4n per thread,
// f32x2 pairs packed along m. Double-buffered e tiles via cp.async.
// __launch_bounds__(256, 3): ~80 regs -> 3 CTAs (24 warps) per SM.
// ---------------------------------------------------------------------------
extern __shared__ float sm[];

__global__ __launch_bounds__(256, 3) void vq_main_kernel(
    const float* __restrict__ x,     // [b, c, h, w] fp32
    const float* __restrict__ emb,   // [K, D] fp32
    float* __restrict__ out)
{
    float* xs = sm;                       // [64][XPITCH]
    float* es = sm + D * XPITCH;          // [2][64][64] double-buffered e tiles
    __shared__ float rs[MT];              // row sums ||x||^2
    __shared__ float e2s[2][NT];          // code norms (double-buffered)
    __shared__ int   idxRow[MT];          // final argmin per row

    const int tid = threadIdx.x;
    const int p0  = blockIdx.x * MT;
    const int b   = p0 >> 12;
    const int s0  = p0 & 4095;
    const float* xbase = x + (size_t)b * 64 * HW + s0;

    const uint32_t es_u32  = (uint32_t)__cvta_generic_to_shared(es);
    const uint32_t e2s_u32 = (uint32_t)__cvta_generic_to_shared(e2s);

    // ---- prefetch e tile 0 (1024 float4s, 4 per thread) ----
    {
        const float* src = g_eT;            // tile 0 at column offset 0
#pragma unroll
        for (int i = 0; i < 4; ++i) {
            int f = tid + i * 256;          // 16 float4 per d-row
            int d = f >> 4, nf = f & 15;
            cp_async16(es_u32 + (uint32_t)(d * NT + nf * 4) * 4, src + d * K + nf * 4);
        }
        if (tid < 16)
            cp_async16(e2s_u32 + (uint32_t)(tid * 4) * 4, g_e2 + tid * 4);
        cp_commit();
    }

    // ---- load x tile with float4: per channel d, 128 contiguous floats ----
#pragma unroll
    for (int i = 0; i < 8; ++i) {
        int f = tid + i * 256;              // 2048 float4s
        int d = f >> 5, mf = f & 31;
        float4 v = *(const float4*)(xbase + d * HW + mf * 4);
        *(float4*)(xs + d * XPITCH + mf * 4) = v;
    }
    __syncthreads();

    // ---- per-row ||x||^2 (sequential d; uniform per-row shift, order benign) ----
    if (tid < MT) {
        float s = 0.0f;
#pragma unroll
        for (int d = 0; d < D; ++d) {
            float v = xs[d * XPITCH + tid];
            s = fmaf(v, v, s);
        }
        rs[tid] = s;
    }

    const int tx = tid & 15;   // n-group: codes tx*4 .. tx*4+3 within tile
    const int ty = tid >> 4;   // m-group: rows  ty*8 .. ty*8+7

    float bestv[8];
    int   besti[8];
#pragma unroll
    for (int i = 0; i < 8; ++i) { bestv[i] = 3.4e38f; besti[i] = 0; }

    for (int nt = 0; nt < K / NT; ++nt) {
        const int buf = nt & 1;
        __syncthreads();   // all warps done with tile nt-1 -> other buffer free (publishes rs/xs on nt=0)

        if (nt < K / NT - 1) {
            // prefetch tile nt+1 into the other buffer
            const float* src = g_eT + (nt + 1) * NT;
            uint32_t dst = es_u32 + (uint32_t)(buf ^ 1) * ES_TILE * 4;
#pragma unroll
            for (int i = 0; i < 4; ++i) {
                int f = tid + i * 256;
                int d = f >> 4, nf = f & 15;
                cp_async16(dst + (uint32_t)(d * NT + nf * 4) * 4, src + d * K + nf * 4);
            }
            if (tid < 16)
                cp_async16(e2s_u32 + (uint32_t)((buf ^ 1) * NT + tid * 4) * 4,
                           g_e2 + (nt + 1) * NT + tid * 4);
            cp_commit();
            asm volatile("cp.async.wait_group 1;" ::: "memory");   // tile nt complete
        } else {
            asm volatile("cp.async.wait_group 0;" ::: "memory");
        }
        __syncthreads();   // tile nt visible to all warps

        const float* esb = es + buf * ES_TILE;
        const float* e2b = e2s[buf];

        // ---- 8m x 4n register tile, f32x2 packed along m ----
        unsigned long long acc[4][4];
#pragma unroll
        for (int mp = 0; mp < 4; ++mp)
#pragma unroll
            for (int j = 0; j < 4; ++j) acc[mp][j] = 0ULL;

#pragma unroll 4
        for (int d = 0; d < D; ++d) {
            const float* xrow = xs + d * XPITCH + ty * 8;
            ulonglong2 xA = *(const ulonglong2*)(xrow);       // rows (0,1),(2,3)
            ulonglong2 xB = *(const ulonglong2*)(xrow + 4);   // rows (4,5),(6,7)
            unsigned long long ax[4] = { xA.x, xA.y, xB.x, xB.y };

            float4 e0 = *(const float4*)(esb + d * NT + tx * 4);
            float ev[4] = { e0.x, e0.y, e0.z, e0.w };
#pragma unroll
            for (int j = 0; j < 4; ++j) {
                unsigned long long bv;
                asm("mov.b64 %0, {%1, %1};" : "=l"(bv) : "f"(ev[j]));
#pragma unroll
                for (int mp = 0; mp < 4; ++mp)
                    asm("fma.rn.f32x2 %0, %1, %2, %0;"
                        : "+l"(acc[mp][j]) : "l"(ax[mp]), "l"(bv));
            }
        }

        // ---- distances + running argmin (ascending n, strict < keeps first) ----
#pragma unroll
        for (int j = 0; j < 4; ++j) {
            int n = nt * NT + tx * 4 + j;
            float e2 = e2b[tx * 4 + j];
#pragma unroll
            for (int mp = 0; mp < 4; ++mp) {
                float2 dv = *(float2*)&acc[mp][j];
                // reference association: (||x||^2 + ||e||^2) - 2*dot, one rounding each
                float t0 = rs[ty * 8 + 2 * mp]     + e2;
                float t1 = rs[ty * 8 + 2 * mp + 1] + e2;
                float d0 = fmaf(dv.x, -2.0f, t0);
                float d1 = fmaf(dv.y, -2.0f, t1);
                if (d0 < bestv[2 * mp])     { bestv[2 * mp]     = d0; besti[2 * mp]     = n; }
                if (d1 < bestv[2 * mp + 1]) { bestv[2 * mp + 1] = d1; besti[2 * mp + 1] = n; }
            }
        }
    }

    // ---- cross-thread argmin reduce (reuse es as scratch; 16KB <= 32KB) ----
    __syncthreads();
    float* redv = es;                 // [128][16]
    int*   redi = (int*)(es + 2048);  // [128][16]
#pragma unroll
    for (int i = 0; i < 8; ++i) {
        int m = ty * 8 + i;
        redv[m * 16 + tx] = bestv[i];
        redi[m * 16 + tx] = besti[i];
    }
    __syncthreads();
    if (tid < MT) {
        float bv = redv[tid * 16];
        int   bi = redi[tid * 16];
#pragma unroll
        for (int t = 1; t < 16; ++t) {
            float v = redv[tid * 16 + t];
            int   ii = redi[tid * 16 + t];
            if (v < bv || (v == bv && ii < bi)) { bv = v; bi = ii; }
        }
        idxRow[tid] = bi;
        out[IOFF + p0 + tid] = (float)bi;   // idx as float (output dtype f32)
    }
    __syncthreads();

    // ---- loss (b,h,w,c): 64 contiguous floats per row ----
#pragma unroll
    for (int i = 0; i < 32; ++i) {
        int idx = tid + i * 256;
        int m = idx >> 6, c = idx & 63;
        float xv = xs[c * XPITCH + m];
        float ev = emb[idxRow[m] * D + c];
        float df = ev - xv;                 // (quantized - x), one rounding
        float t  = df * df;
        out[LOFF + (size_t)(p0 + m) * 64 + c] = t + 0.25f * t;  // == round(1.25*t)
    }

    // ---- quantized_out (b,c,h,w): per channel, 128 contiguous floats ----
#pragma unroll
    for (int i = 0; i < 32; ++i) {
        int idx = tid + i * 256;
        int c = idx >> 7, m = idx & 127;
        float xv = xs[c * XPITCH + m];
        float ev = emb[idxRow[m] * D + c];
        // straight-through: x + (q - x), NOT q (last-ulp fidelity to reference)
        out[(size_t)(b * 64 + c) * HW + s0 + m] = xv + (ev - xv);
    }
}

// ---------------------------------------------------------------------------
extern "C" void kernel_launch(void* const* d_in, const int* in_sizes, int n_in,
                              void* d_out, int out_size)
{
    const float* x_in = (const float*)d_in[0];   // inputs  [32,64,64,64]
    const float* emb  = (const float*)d_in[1];   // embedding [1024,64]
    float* out = (float*)d_out;

    static bool attr_set = false;
    // xs: 64*132*4 = 33792B, es: 2*4096*4 = 32768B -> 66560B/CTA (3 CTAs ~= 195KB)
    size_t smem_bytes = (size_t)(D * XPITCH + 2 * ES_TILE) * sizeof(float);
    if (!attr_set) {
        cudaFuncSetAttribute(vq_main_kernel,
                             cudaFuncAttributeMaxDynamicSharedMemorySize,
                             (int)smem_bytes);
        attr_set = true;
    }

    vq_prep_kernel<<<260, 256>>>(emb);
    vq_main_kernel<<<NROWS / MT, 256, smem_bytes>>>(x_in, emb, out);
}

// round 12
// speedup vs baseline: 2.6358x; 1.4689x over previous
#include <cuda_runtime.h>
#include <cuda_bf16.h>
#include <cstdint>

// Problem constants
#define D      64
#define K      1024
#define HW     4096        // 64*64
#define NROWS  131072      // 32*64*64
#define MT     128         // rows per block
#define NT     64          // codes per tile
#define NTILES 16
#define XPITCH 132         // padded pitch for xs
#define BS_U32 2048        // B tile size in u32 (8KB)
#define CAP    16          // candidate slots per row

// Output layout (concatenated, float32): quantized_out (b,c,h,w), loss (b,h,w,c), idx (b,h,w)
#define LOFF   8388608
#define IOFF   16777216

// Scratch (no cudaMalloc allowed)
// g_eB: bf16 B fragments, mma.m16n8k16-ready.
// Index gid = ((nb*4 + kc)*32 + lane); g_eB[gid*2+{0,1}] = {b0, b1} for that lane:
//   n = nb*8 + lane/4, kb = kc*16 + (lane%4)*2
//   b0 = bf16x2{lo=e[n][kb], hi=e[n][kb+1]}, b1 = {e[n][kb+8], e[n][kb+9]}
__device__ uint32_t g_eB[(K / 8) * 4 * 32 * 2];   // 32768 u32 = 128KB
__device__ float    g_e2[K];                      // ||e_k||^2 (exact fp32 chain)
__device__ int      g_e2max_bits;                 // max ||e||^2 as float bits (monotone for >=0)

static __device__ __forceinline__ uint32_t bf2(float hi, float lo) {
    uint32_t r;
    asm("cvt.rn.satfinite.bf16x2.f32 %0, %1, %2;" : "=r"(r) : "f"(hi), "f"(lo));
    return r;
}
__device__ __forceinline__ void cp_async16(uint32_t saddr, const void* gaddr) {
    asm volatile("cp.async.cg.shared.global [%0], [%1], 16;" :: "r"(saddr), "l"(gaddr) : "memory");
}
__device__ __forceinline__ void cp_commit() {
    asm volatile("cp.async.commit_group;" ::: "memory");
}
__device__ __forceinline__ void mma_bf16(float& c0, float& c1, float& c2, float& c3,
                                         uint32_t a0, uint32_t a1, uint32_t a2, uint32_t a3,
                                         uint32_t b0, uint32_t b1) {
    asm("mma.sync.aligned.m16n8k16.row.col.f32.bf16.bf16.f32 "
        "{%0,%1,%2,%3},{%4,%5,%6,%7},{%8,%9},{%0,%1,%2,%3};"
        : "+f"(c0), "+f"(c1), "+f"(c2), "+f"(c3)
        : "r"(a0), "r"(a1), "r"(a2), "r"(a3), "r"(b0), "r"(b1));
}

// ---------------------------------------------------------------------------
// Prep: pack bf16 B fragments + exact e2 (sequential d chain, matches ref) + e2max.
// ---------------------------------------------------------------------------
__global__ void vq_prep_kernel(const float* __restrict__ emb) {
    int tid = threadIdx.x;
    if (blockIdx.x < 64) {
        int gid  = blockIdx.x * 256 + tid;      // 0..16383
        int lane = gid & 31, kc = (gid >> 5) & 3, nb = gid >> 7;
        int n  = nb * 8 + (lane >> 2);
        int kb = kc * 16 + (lane & 3) * 2;
        const float* e = emb + n * D + kb;
        g_eB[gid * 2]     = bf2(e[1], e[0]);
        g_eB[gid * 2 + 1] = bf2(e[9], e[8]);
    } else {
        int k = (blockIdx.x - 64) * 256 + tid;  // blocks 64..67 -> k 0..1023
        float4 v[16];
        const float4* row = (const float4*)(emb + k * D);
#pragma unroll
        for (int i = 0; i < 16; ++i) v[i] = row[i];
        float s = 0.0f;
#pragma unroll
        for (int i = 0; i < 16; ++i) {          // sequential d = 0..63 (reference order)
            s = fmaf(v[i].x, v[i].x, s);
            s = fmaf(v[i].y, v[i].y, s);
            s = fmaf(v[i].z, v[i].z, s);
            s = fmaf(v[i].w, v[i].w, s);
        }
        g_e2[k] = s;
        atomicMax(&g_e2max_bits, __float_as_int(s));
    }
}

// ---------------------------------------------------------------------------
// Main kernel: bf16 MMA approx distances (2 passes: min, then candidate
// collection under a rigorous error margin), exact fp32-chain recheck of
// candidates (reference-rounded), then R10's epilogue.
// ---------------------------------------------------------------------------
extern __shared__ float sm[];

__global__ __launch_bounds__(256, 3) void vq_main_kernel(
    const float* __restrict__ x,     // [b, c, h, w] fp32
    const float* __restrict__ emb,   // [K, D] fp32
    float* __restrict__ out)
{
    float*    xs = sm;                            // [64][XPITCH]
    uint32_t* Bs = (uint32_t*)(sm + D * XPITCH);  // [2][2048] double-buffered B tiles
    __shared__ float e2sh[2][NT];
    __shared__ float rs[MT];
    __shared__ float thrS[MT];
    __shared__ int   ccount[MT];
    __shared__ int   cidx[MT * CAP];
    __shared__ int   idxRow[MT];

    const int tid = threadIdx.x;
    const int p0  = blockIdx.x * MT;
    const int b   = p0 >> 12;
    const int s0  = p0 & 4095;
    const float* xbase = x + (size_t)b * 64 * HW + s0;

    const uint32_t bs_u = (uint32_t)__cvta_generic_to_shared(Bs);
    const uint32_t e2_u = (uint32_t)__cvta_generic_to_shared(e2sh);

    if (tid < MT) ccount[tid] = 0;

    // ---- prefetch B tile 0 + e2 tile 0 ----
    {
#pragma unroll
        for (int i = 0; i < 2; ++i) {
            int c = tid + i * 256;                // 512 chunks of 16B
            cp_async16(bs_u + (uint32_t)c * 16, g_eB + c * 4);
        }
        if (tid < 16) cp_async16(e2_u + (uint32_t)tid * 16, g_e2 + tid * 4);
        cp_commit();
    }

    // ---- load x tile (float4): per channel d, 128 contiguous floats ----
#pragma unroll
    for (int i = 0; i < 8; ++i) {
        int f = tid + i * 256;
        int d = f >> 5, mf = f & 31;
        float4 v = *(const float4*)(xbase + d * HW + mf * 4);
        *(float4*)(xs + d * XPITCH + mf * 4) = v;
    }
    __syncthreads();

    // ---- per-row ||x||^2 (sequential d, reference order) ----
    if (tid < MT) {
        float s = 0.0f;
#pragma unroll
        for (int d = 0; d < D; ++d) {
            float v = xs[d * XPITCH + tid];
            s = fmaf(v, v, s);
        }
        rs[tid] = s;
    }

    // ---- build A fragments (bf16 of x), hoisted for full K ----
    const int t = tid & 31, w = tid >> 5;
    const int r = w * 16 + (t >> 2);   // this thread's first row (and r+8)
    const int q = (t & 3) * 2;         // col pair base within 8-wide n-block
    uint32_t A[4][4];
#pragma unroll
    for (int kc = 0; kc < 4; ++kc) {
        int k = kc * 16 + q;
        A[kc][0] = bf2(xs[(k + 1) * XPITCH + r],     xs[k * XPITCH + r]);
        A[kc][1] = bf2(xs[(k + 1) * XPITCH + r + 8], xs[k * XPITCH + r + 8]);
        A[kc][2] = bf2(xs[(k + 9) * XPITCH + r],     xs[(k + 8) * XPITCH + r]);
        A[kc][3] = bf2(xs[(k + 9) * XPITCH + r + 8], xs[(k + 8) * XPITCH + r + 8]);
    }

    float rbest0 = 3.4e38f, rbest1 = 3.4e38f;

    // ================= PASS 1: approx min per row =================
    for (int nt = 0; nt < NTILES; ++nt) {
        const int buf = nt & 1;
        __syncthreads();
        if (nt < NTILES - 1) {
            const uint32_t* src = g_eB + (nt + 1) * BS_U32;
            uint32_t dst = bs_u + (uint32_t)(buf ^ 1) * 8192;
#pragma unroll
            for (int i = 0; i < 2; ++i) {
                int c = tid + i * 256;
                cp_async16(dst + (uint32_t)c * 16, src + c * 4);
            }
            if (tid < 16)
                cp_async16(e2_u + (uint32_t)((buf ^ 1) * NT + tid * 4) * 4,
                           g_e2 + (nt + 1) * NT + tid * 4);
            cp_commit();
            asm volatile("cp.async.wait_group 1;" ::: "memory");
        } else {
            asm volatile("cp.async.wait_group 0;" ::: "memory");
        }
        __syncthreads();

        const uint32_t* bp  = Bs + buf * BS_U32;
        const float*    e2p = e2sh[buf];
#pragma unroll
        for (int nbl = 0; nbl < 8; ++nbl) {
            float c0 = 0.f, c1 = 0.f, c2 = 0.f, c3 = 0.f;
#pragma unroll
            for (int kc = 0; kc < 4; ++kc) {
                uint2 bb = *(const uint2*)(bp + ((nbl * 4 + kc) * 32 + t) * 2);
                mma_bf16(c0, c1, c2, c3, A[kc][0], A[kc][1], A[kc][2], A[kc][3], bb.x, bb.y);
            }
            float2 e2v = *(const float2*)(e2p + nbl * 8 + q);
            float v0 = fmaf(c0, -2.f, e2v.x), v1 = fmaf(c1, -2.f, e2v.y);
            float v2 = fmaf(c2, -2.f, e2v.x), v3 = fmaf(c3, -2.f, e2v.y);
            rbest0 = fminf(rbest0, fminf(v0, v1));
            rbest1 = fminf(rbest1, fminf(v2, v3));
        }
    }

    // combine row-min across the 4 lanes sharing each row
    rbest0 = fminf(rbest0, __shfl_xor_sync(0xffffffff, rbest0, 1));
    rbest0 = fminf(rbest0, __shfl_xor_sync(0xffffffff, rbest0, 2));
    rbest1 = fminf(rbest1, __shfl_xor_sync(0xffffffff, rbest1, 1));
    rbest1 = fminf(rbest1, __shfl_xor_sync(0xffffffff, rbest1, 2));
    {
        float emax = sqrtf(__int_as_float(g_e2max_bits));
        if ((t & 3) == 0) {
            // margin: 4u*||x||*||e||max (u=2^-8 bf16 RN) + slack; floor keeps it generous
            float m0 = fmaxf(0.016f * sqrtf(rs[r])     * emax + 1e-4f, 5e-4f);
            float m1 = fmaxf(0.016f * sqrtf(rs[r + 8]) * emax + 1e-4f, 5e-4f);
            thrS[r]     = rbest0 + 2.f * m0;
            thrS[r + 8] = rbest1 + 2.f * m1;
        }
    }
    __syncthreads();
    const float thr0 = thrS[r], thr1 = thrS[r + 8];

    // prefetch tile 0 for pass 2 (pipeline drained; buffers free)
    {
#pragma unroll
        for (int i = 0; i < 2; ++i) {
            int c = tid + i * 256;
            cp_async16(bs_u + (uint32_t)c * 16, g_eB + c * 4);
        }
        if (tid < 16) cp_async16(e2_u + (uint32_t)tid * 16, g_e2 + tid * 4);
        cp_commit();
    }

    // ================= PASS 2: collect candidates <= thr =================
    for (int nt = 0; nt < NTILES; ++nt) {
        const int buf = nt & 1;
        __syncthreads();
        if (nt < NTILES - 1) {
            const uint32_t* src = g_eB + (nt + 1) * BS_U32;
            uint32_t dst = bs_u + (uint32_t)(buf ^ 1) * 8192;
#pragma unroll
            for (int i = 0; i < 2; ++i) {
                int c = tid + i * 256;
                cp_async16(dst + (uint32_t)c * 16, src + c * 4);
            }
            if (tid < 16)
                cp_async16(e2_u + (uint32_t)((buf ^ 1) * NT + tid * 4) * 4,
                           g_e2 + (nt + 1) * NT + tid * 4);
            cp_commit();
            asm volatile("cp.async.wait_group 1;" ::: "memory");
        } else {
            asm volatile("cp.async.wait_group 0;" ::: "memory");
        }
        __syncthreads();

        const uint32_t* bp  = Bs + buf * BS_U32;
        const float*    e2p = e2sh[buf];
#pragma unroll
        for (int nbl = 0; nbl < 8; ++nbl) {
            float c0 = 0.f, c1 = 0.f, c2 = 0.f, c3 = 0.f;
#pragma unroll
            for (int kc = 0; kc < 4; ++kc) {
                uint2 bb = *(const uint2*)(bp + ((nbl * 4 + kc) * 32 + t) * 2);
                mma_bf16(c0, c1, c2, c3, A[kc][0], A[kc][1], A[kc][2], A[kc][3], bb.x, bb.y);
            }
            float2 e2v = *(const float2*)(e2p + nbl * 8 + q);
            float v0 = fmaf(c0, -2.f, e2v.x), v1 = fmaf(c1, -2.f, e2v.y);
            float v2 = fmaf(c2, -2.f, e2v.x), v3 = fmaf(c3, -2.f, e2v.y);
            int n0 = nt * NT + nbl * 8 + q;
            if (v0 <= thr0) { int sl = atomicAdd(&ccount[r], 1);     if (sl < CAP) cidx[r * CAP + sl] = n0; }
            if (v1 <= thr0) { int sl = atomicAdd(&ccount[r], 1);     if (sl < CAP) cidx[r * CAP + sl] = n0 + 1; }
            if (v2 <= thr1) { int sl = atomicAdd(&ccount[r + 8], 1); if (sl < CAP) cidx[(r + 8) * CAP + sl] = n0; }
            if (v3 <= thr1) { int sl = atomicAdd(&ccount[r + 8], 1); if (sl < CAP) cidx[(r + 8) * CAP + sl] = n0 + 1; }
        }
    }

    // ================= EXACT phase: reference-rounded recheck =================
    __syncthreads();
    float* dex = (float*)Bs;    // overlay: 2048 floats scratch (B tiles no longer needed)
#pragma unroll
    for (int i = 0; i < 8; ++i) {
        int slot = tid + i * 256;            // 0..2047
        int m = slot >> 4, sl = slot & 15;
        int cnt = ccount[m];
        if (cnt <= CAP && sl < cnt) {
            int n = cidx[m * CAP + sl];
            const float* ep = emb + n * D;
            float dot = 0.f;
#pragma unroll 8
            for (int d = 0; d < D; ++d) dot = fmaf(xs[d * XPITCH + m], ep[d], dot);
            // reference association: (rs + e2) one rounding, then fmaf(dot,-2,.)
            dex[slot] = fmaf(dot, -2.f, rs[m] + g_e2[n]);
        }
    }
    __syncthreads();
    if (tid < MT) {
        int m = tid, cnt = ccount[m];
        float bv = 3.4e38f; int bi = 0;
        if (cnt <= CAP) {
            for (int sl = 0; sl < cnt; ++sl) {
                float v = dex[m * 16 + sl];
                int   n = cidx[m * CAP + sl];
                if (v < bv || (v == bv && n < bi)) { bv = v; bi = n; }
            }
        } else {
            // fallback (probability ~0): full exact scan, ascending n, strict <
            for (int n = 0; n < K; ++n) {
                const float* ep = emb + n * D;
                float dot = 0.f;
                for (int d = 0; d < D; ++d) dot = fmaf(xs[d * XPITCH + m], ep[d], dot);
                float v = fmaf(dot, -2.f, rs[m] + g_e2[n]);
                if (v < bv) { bv = v; bi = n; }
            }
        }
        idxRow[m] = bi;
        out[IOFF + p0 + m] = (float)bi;
    }
    __syncthreads();

    // ---- loss (b,h,w,c): 64 contiguous floats per row ----
#pragma unroll
    for (int i = 0; i < 32; ++i) {
        int idx = tid + i * 256;
        int m = idx >> 6, c = idx & 63;
        float xv = xs[c * XPITCH + m];
        float ev = emb[idxRow[m] * D + c];
        float df = ev - xv;
        float tt = df * df;
        out[LOFF + (size_t)(p0 + m) * 64 + c] = tt + 0.25f * tt;
    }

    // ---- quantized_out (b,c,h,w): per channel, 128 contiguous floats ----
#pragma unroll
    for (int i = 0; i < 32; ++i) {
        int idx = tid + i * 256;
        int c = idx >> 7, m = idx & 127;
        float xv = xs[c * XPITCH + m];
        float ev = emb[idxRow[m] * D + c];
        out[(size_t)(b * 64 + c) * HW + s0 + m] = xv + (ev - xv);
    }
}

// ---------------------------------------------------------------------------
extern "C" void kernel_launch(void* const* d_in, const int* in_sizes, int n_in,
                              void* d_out, int out_size)
{
    const float* x_in = (const float*)d_in[0];   // inputs  [32,64,64,64]
    const float* emb  = (const float*)d_in[1];   // embedding [1024,64]
    float* out = (float*)d_out;

    static bool attr_set = false;
    // dynamic smem: xs 33792B + B tiles 2*8192B = 50176B (3 CTAs with ~10.5KB static)
    size_t smem_bytes = (size_t)(D * XPITCH * 4 + 2 * 8192);
    if (!attr_set) {
        cudaFuncSetAttribute(vq_main_kernel,
                             cudaFuncAttributeMaxDynamicSharedMemorySize,
                             (int)smem_bytes);
        attr_set = true;
    }

    vq_prep_kernel<<<68, 256>>>(emb);
    vq_main_kernel<<<NROWS / MT, 256, smem_bytes>>>(x_in, emb, out);
}